// round 13
// baseline (speedup 1.0000x reference)
#include <cuda_runtime.h>
#include <cuda_bf16.h>
#include <math.h>
#include <stdint.h>

#define TOK 32768      // B*N = 4*8192
#define DIM 256
#define HIDW 512
#define H2 1024
#define QKD 64
#define NCAT (H2+QKD)  // 1088 combined gemm01 output width
#define GRP 256
#define NG 32          // groups per sequence
#define NBATCH 4
#define NLAYER 8
#define WLAYER (NCAT*DIM + HIDW*DIM)   // 409600
#define WTOT (NLAYER*WLAYER)

// ---------------- scratch (device globals only; no allocation) -------------
__device__ float g_h[TOK*DIM];
__device__ float g_hid[TOK*H2];
__device__ float g_qk[TOK*QKD];
__device__ float g_quad[TOK*HIDW];
__device__ float g_kv[NBATCH*NG*QKD*HIDW];
__device__ float g_bias8[NLAYER*GRP*GRP];
__device__ float g_bcat[NLAYER*NCAT];
__device__ float g_part[NBATCH*NG*DIM];
// pre-split bf16 operands
__device__ __nv_bfloat16 g_axh[TOK*DIM],  g_axl[TOK*DIM];    // ln output
__device__ __nv_bfloat16 g_aqh[TOK*HIDW], g_aql[TOK*HIDW];   // gated quad+lin
__device__ __nv_bfloat16 g_wh[WTOT], g_wl[WTOT];             // packed weights [n][k]

__device__ __forceinline__ float siluf(float x){ return x/(1.0f+expf(-x)); }

// ---------------- weight prep: ALL groups in one launch --------------------
// blockIdx.z = layer*3 + group. Transpose [K][N] -> [n][k] bf16 hi/lo.
__global__ void wprep_all(const float* __restrict__ Wh, const float* __restrict__ Wqk,
                          const float* __restrict__ Wo){
  int z = blockIdx.z;
  int l = z/3, grp = z - l*3;
  int K, N, dstBase;
  const float* W;
  if (grp == 0){ W = Wh  + (size_t)l*DIM*H2;   K = DIM;  N = H2;  dstBase = 0; }
  else if (grp == 1){ W = Wqk + (size_t)l*DIM*QKD; K = DIM;  N = QKD; dstBase = H2*DIM; }
  else { W = Wo  + (size_t)l*HIDW*DIM; K = HIDW; N = DIM; dstBase = NCAT*DIM; }
  int n0 = blockIdx.x*32, k0 = blockIdx.y*32;
  if (n0 >= N || k0 >= K) return;
  size_t dbase = (size_t)l*WLAYER + dstBase;
  __shared__ float t[32][33];
  int tx = threadIdx.x, ty = threadIdx.y;   // 32 x 8
  #pragma unroll
  for (int i=0;i<32;i+=8)
    t[ty+i][tx] = W[(size_t)(k0+ty+i)*N + n0+tx];
  __syncthreads();
  #pragma unroll
  for (int i=0;i<32;i+=8){
    float v = t[tx][ty+i];
    __nv_bfloat16 h = __float2bfloat16(v);
    float hf = __bfloat162float(h);
    size_t o = dbase + (size_t)(n0+ty+i)*K + k0+tx;
    g_wh[o] = h;
    g_wl[o] = __float2bfloat16(v - hf);
  }
}

// ---------------- misc prep: rel-pos bias tables + concat biases -----------
__global__ void misc_prep(const float* __restrict__ relb, const float* __restrict__ bh,
                          const float* __restrict__ bqk){
  int i = blockIdx.x, l = blockIdx.y, j = threadIdx.x;
  int n = i - j; if (n < 0) n = 0;
  int bucket;
  if (n < 16) bucket = n;
  else {
    float t = logf((float)n * (1.0f/16.0f)) * (16.0f / 2.0794415416798357f); // /log(8)
    int val = 16 + (int)t;
    bucket = val < 31 ? val : 31;
  }
  g_bias8[((size_t)l*GRP + i)*GRP + j] = relb[l*32 + bucket]*8.0f;   // * sqrt(QKD)
  int idx = i*GRP + j;
  if (idx < NCAT)
    g_bcat[l*NCAT + idx] = (idx < H2) ? bh[l*H2 + idx] : bqk[l*QKD + idx - H2];
}

// ---------------- fused embed + layer-0 layernorm --------------------------
__global__ void embed_ln_kernel(const float* __restrict__ x, const float* __restrict__ W,
                                const float* __restrict__ be, const float* __restrict__ pos,
                                const float* __restrict__ gl, const float* __restrict__ bl){
  int row = blockIdx.x;
  int n = row & 8191;
  int d = threadIdx.x;
  __shared__ float xs[8];
  __shared__ float red[8];
  if (d < 5) xs[d] = x[row*5+d];
  __syncthreads();
  float v = be[d] + pos[n*DIM+d];
  #pragma unroll
  for (int k=0;k<5;k++) v = fmaf(xs[k], W[k*DIM+d], v);
  g_h[row*DIM+d] = v;
  float s = v;
  #pragma unroll
  for (int o=16;o>0;o>>=1) s += __shfl_xor_sync(0xffffffffu, s, o);
  if ((d&31)==0) red[d>>5] = s;
  __syncthreads();
  float tot = 0.f;
  #pragma unroll
  for (int i=0;i<8;i++) tot += red[i];
  float mu = tot * (1.0f/DIM);
  float dv = v - mu;
  __syncthreads();
  float sq = dv*dv;
  #pragma unroll
  for (int o=16;o>0;o>>=1) sq += __shfl_xor_sync(0xffffffffu, sq, o);
  if ((d&31)==0) red[d>>5] = sq;
  __syncthreads();
  float vt = 0.f;
  #pragma unroll
  for (int i=0;i<8;i++) vt += red[i];
  float var = vt*(1.0f/DIM);
  float y = fmaf(dv*rsqrtf(var+1e-5f), gl[d], bl[d]);
  __nv_bfloat16 h = __float2bfloat16(y);
  g_axh[row*DIM+d] = h;
  g_axl[row*DIM+d] = __float2bfloat16(y - __bfloat162float(h));
}

// ---------------- layernorm (layers 1..7) ----------------------------------
__global__ void ln_kernel(const float* __restrict__ gl, const float* __restrict__ bl){
  int row = blockIdx.x, d = threadIdx.x;
  float v = g_h[row*DIM+d];
  __shared__ float red[8];
  float s = v;
  #pragma unroll
  for (int o=16;o>0;o>>=1) s += __shfl_xor_sync(0xffffffffu, s, o);
  if ((d&31)==0) red[d>>5] = s;
  __syncthreads();
  float tot = 0.f;
  #pragma unroll
  for (int i=0;i<8;i++) tot += red[i];
  float mu = tot * (1.0f/DIM);
  float dv = v - mu;
  __syncthreads();
  float sq = dv*dv;
  #pragma unroll
  for (int o=16;o>0;o>>=1) sq += __shfl_xor_sync(0xffffffffu, sq, o);
  if ((d&31)==0) red[d>>5] = sq;
  __syncthreads();
  float vt = 0.f;
  #pragma unroll
  for (int i=0;i<8;i++) vt += red[i];
  float var = vt*(1.0f/DIM);
  float y = fmaf(dv*rsqrtf(var+1e-5f), gl[d], bl[d]);
  __nv_bfloat16 h = __float2bfloat16(y);
  g_axh[row*DIM+d] = h;
  g_axl[row*DIM+d] = __float2bfloat16(y - __bfloat162float(h));
}

// ---------------- split-bf16 tensor-core GEMM (k-tile 64, pipelined) -------
// C = A@B via Ahi*Bhi + Ahi*Blo + Alo*Bhi (fp32 accum)
// MODE 0: [hid|qk] = silu(nx @ [Wh|Wqk] + bcat)  [32768,256]x[256,1088]
// MODE 2: g_h  += quad @ Wo + bo                 [32768,512]x[512,256]
// CTA 128x64, k-tile 64, 8 warps (4m x 2n), double-buffered smem +
// register prefetch (6x uint4 x hi/lo), ldmatrix.x4. No cp.async.
#define ABUF 4608   // 128*36 u32
#define BBUF 2304   // 64*36 u32
#define GSM ((2*ABUF*2 + 2*BBUF*2)*4)  // 110592 bytes

#define BMMA(acc, a, b0, b1) \
  asm volatile("mma.sync.aligned.m16n8k16.row.col.f32.bf16.bf16.f32 " \
    "{%0,%1,%2,%3}, {%4,%5,%6,%7}, {%8,%9}, {%0,%1,%2,%3};\n" \
    : "+f"(acc[0]),"+f"(acc[1]),"+f"(acc[2]),"+f"(acc[3]) \
    : "r"(a[0]),"r"(a[1]),"r"(a[2]),"r"(a[3]), "r"(b0),"r"(b1))

#define LDSM4(d0,d1,d2,d3,a) \
  asm volatile("ldmatrix.sync.aligned.m8n8.x4.shared.b16 {%0,%1,%2,%3}, [%4];" \
    : "=r"(d0),"=r"(d1),"=r"(d2),"=r"(d3) : "r"(a))

// per thread: A rows (tid>>3)+32i (i=0..3), B rows (tid>>3)+32i (i=0..1), col (tid&7)*8 bf16
#define LDTILE(kt) do{ \
  size_t ko = (size_t)(kt)*64 + ac; \
  pah[0] = *(const uint4*)(Ah + (size_t)(m0+ar0    )*K + ko); \
  pah[1] = *(const uint4*)(Ah + (size_t)(m0+ar0+32 )*K + ko); \
  pah[2] = *(const uint4*)(Ah + (size_t)(m0+ar0+64 )*K + ko); \
  pah[3] = *(const uint4*)(Ah + (size_t)(m0+ar0+96 )*K + ko); \
  pal[0] = *(const uint4*)(Al + (size_t)(m0+ar0    )*K + ko); \
  pal[1] = *(const uint4*)(Al + (size_t)(m0+ar0+32 )*K + ko); \
  pal[2] = *(const uint4*)(Al + (size_t)(m0+ar0+64 )*K + ko); \
  pal[3] = *(const uint4*)(Al + (size_t)(m0+ar0+96 )*K + ko); \
  pbh[0] = *(const uint4*)(Bh_ + (size_t)(n0+ar0   )*K + ko); \
  pbh[1] = *(const uint4*)(Bh_ + (size_t)(n0+ar0+32)*K + ko); \
  pbl[0] = *(const uint4*)(Bl_ + (size_t)(n0+ar0   )*K + ko); \
  pbl[1] = *(const uint4*)(Bl_ + (size_t)(n0+ar0+32)*K + ko); \
}while(0)

#define STTILE(buf) do{ \
  *(uint4*)&AH[(buf)*ABUF + (ar0    )*36 + acu] = pah[0]; \
  *(uint4*)&AH[(buf)*ABUF + (ar0+32 )*36 + acu] = pah[1]; \
  *(uint4*)&AH[(buf)*ABUF + (ar0+64 )*36 + acu] = pah[2]; \
  *(uint4*)&AH[(buf)*ABUF + (ar0+96 )*36 + acu] = pah[3]; \
  *(uint4*)&AL[(buf)*ABUF + (ar0    )*36 + acu] = pal[0]; \
  *(uint4*)&AL[(buf)*ABUF + (ar0+32 )*36 + acu] = pal[1]; \
  *(uint4*)&AL[(buf)*ABUF + (ar0+64 )*36 + acu] = pal[2]; \
  *(uint4*)&AL[(buf)*ABUF + (ar0+96 )*36 + acu] = pal[3]; \
  *(uint4*)&BH[(buf)*BBUF + (ar0    )*36 + acu] = pbh[0]; \
  *(uint4*)&BH[(buf)*BBUF + (ar0+32 )*36 + acu] = pbh[1]; \
  *(uint4*)&BL[(buf)*BBUF + (ar0    )*36 + acu] = pbl[0]; \
  *(uint4*)&BL[(buf)*BBUF + (ar0+32 )*36 + acu] = pbl[1]; \
}while(0)

template<int MODE>
__global__ void __launch_bounds__(256) mma_gemm(int woff, const float* __restrict__ bias_p,
                                                int lay){
  constexpr int K  = (MODE==2)?HIDW:DIM;
  constexpr int KT = K/64;

  const __nv_bfloat16* Ah = (MODE==2)? g_aqh : g_axh;
  const __nv_bfloat16* Al = (MODE==2)? g_aql : g_axl;
  const __nv_bfloat16* Bh_ = g_wh + woff;
  const __nv_bfloat16* Bl_ = g_wl + woff;
  const float* bias = (MODE==0) ? (g_bcat + lay*NCAT) : bias_p;

  extern __shared__ uint32_t smu[];
  uint32_t* AH = smu;
  uint32_t* AL = smu + 2*ABUF;
  uint32_t* BH = smu + 4*ABUF;
  uint32_t* BL = smu + 4*ABUF + 2*BBUF;
  uint32_t smb = (uint32_t)__cvta_generic_to_shared(smu);

  int tid = threadIdx.x;
  int warp = tid>>5, lane = tid&31;
  int gq = lane>>2, tig = lane&3;
  int wm = (warp>>1)*32, wn = (warp&1)*32;
  int m0 = blockIdx.y*128, n0 = blockIdx.x*64;

  int ar0 = tid>>3;            // row within 32-row slab
  int ac  = (tid&7)*8;         // bf16 col within k-tile (64 wide)
  int acu = (tid&7)*4;         // u32 col

  // ldmatrix per-lane offsets (u32 units within one buffer)
  int lg = lane>>3, lr = lane&7;
  uint32_t aoff[2], boff[2];
  #pragma unroll
  for (int mt=0;mt<2;mt++)
    aoff[mt] = (uint32_t)((wm + mt*16 + (lg&1)*8 + lr)*36 + (lg>>1)*4);
  #pragma unroll
  for (int p=0;p<2;p++)
    boff[p] = (uint32_t)((wn + p*16 + (lg>>1)*8 + lr)*36 + (lg&1)*4);

  float acc[2][4][4];
  #pragma unroll
  for (int mt=0;mt<2;mt++)
    #pragma unroll
    for (int nt=0;nt<4;nt++)
      #pragma unroll
      for (int c=0;c<4;c++) acc[mt][nt][c]=0.f;

  uint4 pah[4], pal[4], pbh[2], pbl[2];

  LDTILE(0);
  STTILE(0);
  __syncthreads();

  for (int kt=0; kt<KT; kt++){
    int buf = kt&1;
    if (kt+1 < KT) LDTILE(kt+1);

    uint32_t abase  = smb + (buf*ABUF)*4;
    uint32_t albase = smb + ((2+buf)*ABUF)*4;
    uint32_t bbase  = smb + (4*ABUF + buf*BBUF)*4;
    uint32_t blbase = smb + (4*ABUF + (2+buf)*BBUF)*4;

    #pragma unroll
    for (int kk=0;kk<4;kk++){
      uint32_t ah[2][4], al[2][4];
      #pragma unroll
      for (int mt=0;mt<2;mt++){
        LDSM4(ah[mt][0],ah[mt][1],ah[mt][2],ah[mt][3], abase  + (aoff[mt] + kk*8)*4);
        LDSM4(al[mt][0],al[mt][1],al[mt][2],al[mt][3], albase + (aoff[mt] + kk*8)*4);
      }
      uint32_t bh[2][4], bl[2][4];
      #pragma unroll
      for (int p=0;p<2;p++){
        LDSM4(bh[p][0],bh[p][1],bh[p][2],bh[p][3], bbase  + (boff[p] + kk*8)*4);
        LDSM4(bl[p][0],bl[p][1],bl[p][2],bl[p][3], blbase + (boff[p] + kk*8)*4);
      }
      #pragma unroll
      for (int mt=0;mt<2;mt++)
        #pragma unroll
        for (int p=0;p<2;p++)
          #pragma unroll
          for (int h=0;h<2;h++){
            float* a4 = acc[mt][p*2+h];
            BMMA(a4, ah[mt], bh[p][h*2], bh[p][h*2+1]);
            BMMA(a4, ah[mt], bl[p][h*2], bl[p][h*2+1]);
            BMMA(a4, al[mt], bh[p][h*2], bh[p][h*2+1]);
          }
    }
    if (kt+1 < KT) STTILE(buf^1);
    __syncthreads();
  }

  // epilogue
  bool isqk = (MODE==0) && (n0 >= H2);
  #pragma unroll
  for (int mt=0;mt<2;mt++){
    int r0 = m0 + wm + mt*16 + gq;
    #pragma unroll
    for (int nt=0;nt<4;nt++){
      int c0 = n0 + wn + nt*8 + tig*2;
      float b0 = bias[c0], b1 = bias[c0+1];
      #pragma unroll
      for (int h=0;h<2;h++){
        int row = r0 + h*8;
        float v0 = acc[mt][nt][h*2+0] + b0;
        float v1 = acc[mt][nt][h*2+1] + b1;
        if (MODE==2){
          float* p = g_h + (size_t)row*DIM + c0;
          p[0] += v0; p[1] += v1;
        } else if (isqk){
          float* p = g_qk + (size_t)row*QKD + (c0 - H2);
          p[0] = siluf(v0); p[1] = siluf(v1);
        } else {
          float* p = g_hid + (size_t)row*H2 + c0;
          p[0] = siluf(v0); p[1] = siluf(v1);
        }
      }
    }
  }
}

// ---------------- fused quad attention + K^T V -----------------------------
#define SQS 68
#define SAS 260
#define ATTN_SMEM ((256*SQS + 64*SQS + 64*SAS + 64*128 + 6*64)*4)

__global__ void __launch_bounds__(256) attn_kernel(const float* __restrict__ gamma,
                                                   const float* __restrict__ beta,
                                                   int lay){
  extern __shared__ float sm[];
  float* sQK  = sm;                 // [256][68]  raw silu(qk)
  float* sQQ  = sQK + 256*SQS;      // [64][68]   quad queries (this i-tile)
  float* sAtt = sQQ + 64*SQS;       // [64][260]  laplace attn tile
  float* sV   = sAtt + 64*SAS;      // [64][128]  v chunk
  float* sG   = sV + 64*128;        // g0,b0,g2,b2,g3,b3 (6*64)
  int it = blockIdx.x, g = blockIdx.y, b = blockIdx.z;
  int tid = threadIdx.x;
  size_t base = (size_t)(b*NG + g)*GRP;
  const float* btab = g_bias8 + (size_t)lay*GRP*GRP;

  #pragma unroll
  for (int i=0;i<16;i++){
    int idx = i*256+tid;
    int r = idx>>4, c4 = (idx&15)*4;
    *(float4*)&sQK[r*SQS + c4] = *(const float4*)(g_qk + (base+r)*QKD + c4);
  }
  if (tid < 64){
    sG[tid]     = gamma[tid];      sG[64+tid]  = beta[tid];        // head 0 (qq)
    sG[128+tid] = gamma[128+tid];  sG[192+tid] = beta[128+tid];    // head 2 (qk)
    sG[256+tid] = gamma[192+tid];  sG[320+tid] = beta[192+tid];    // head 3 (lk)
  }
  __syncthreads();
  #pragma unroll
  for (int i=0;i<16;i++){
    int idx = i*256+tid; int ii = idx>>6, d = idx&63;
    sQQ[ii*SQS+d] = fmaf(sQK[(it*64+ii)*SQS + d], sG[d], sG[64+d]);
  }
  __syncthreads();

  int ty = tid>>5, tx = tid&31;
  // phase A: sim = qq.qkk/256 + bias -> laplace -> causal mask
  {
    float acc[8][8];
    #pragma unroll
    for (int r=0;r<8;r++)
      #pragma unroll
      for (int c=0;c<8;c++) acc[r][c]=0.f;
    #pragma unroll 4
    for (int d=0; d<64; d++){
      float g2 = sG[128+d], b2 = sG[192+d];
      float a[8], kk[8];
      #pragma unroll
      for (int r=0;r<8;r++) a[r] = sQQ[(ty*8+r)*SQS + d];
      #pragma unroll
      for (int c=0;c<8;c++) kk[c] = fmaf(sQK[(tx + 32*c)*SQS + d], g2, b2);
      #pragma unroll
      for (int r=0;r<8;r++)
        #pragma unroll
        for (int c=0;c<8;c++) acc[r][c] = fmaf(a[r], kk[c], acc[r][c]);
    }
    #pragma unroll
    for (int r=0;r<8;r++){
      int ig = it*64 + ty*8 + r;
      #pragma unroll
      for (int c=0;c<8;c++){
        int j = tx + 32*c;
        float s = acc[r][c]*(1.0f/256.0f) + btab[ig*GRP + j];
        float at = (j <= ig) ? 0.5f*(1.0f + erff((s - 0.70710678f)*0.79788456f)) : 0.0f;
        sAtt[(ty*8+r)*SAS + j] = at;
      }
    }
  }

  float g3r[8], b3r[8];
  #pragma unroll
  for (int r=0;r<8;r++){ g3r[r]=sG[256+ty*8+r]; b3r[r]=sG[320+ty*8+r]; }

  // phase B: quad = attn @ v, plus (it==0) kv = lk^T v / 256
  for (int et=0; et<4; et++){
    float qacc[8][4], kvacc[8][4];
    #pragma unroll
    for (int r=0;r<8;r++)
      #pragma unroll
      for (int c=0;c<4;c++){ qacc[r][c]=0.f; kvacc[r][c]=0.f; }
    for (int jc=0;jc<4;jc++){
      __syncthreads();
      #pragma unroll
      for (int i=0;i<8;i++){
        int idx = i*256+tid;
        int r = idx>>5, c4 = (idx&31)*4;
        *(float4*)&sV[r*128+c4] = *(const float4*)(g_hid + (base + jc*64 + r)*H2 + et*128 + c4);
      }
      __syncthreads();
      #pragma unroll 2
      for (int jj=0;jj<64;jj++){
        int j = jc*64 + jj;
        float4 v4 = *(float4*)&sV[jj*128 + tx*4];
        float a[8];
        #pragma unroll
        for (int r=0;r<8;r++) a[r] = sAtt[(ty*8+r)*SAS + j];
        #pragma unroll
        for (int r=0;r<8;r++){
          qacc[r][0]=fmaf(a[r],v4.x,qacc[r][0]);
          qacc[r][1]=fmaf(a[r],v4.y,qacc[r][1]);
          qacc[r][2]=fmaf(a[r],v4.z,qacc[r][2]);
          qacc[r][3]=fmaf(a[r],v4.w,qacc[r][3]);
        }
        if (it==0){
          #pragma unroll
          for (int r=0;r<8;r++){
            float lk = fmaf(sQK[j*SQS + ty*8 + r], g3r[r], b3r[r]);
            kvacc[r][0]=fmaf(lk,v4.x,kvacc[r][0]);
            kvacc[r][1]=fmaf(lk,v4.y,kvacc[r][1]);
            kvacc[r][2]=fmaf(lk,v4.z,kvacc[r][2]);
            kvacc[r][3]=fmaf(lk,v4.w,kvacc[r][3]);
          }
        }
      }
    }
    #pragma unroll
    for (int r=0;r<8;r++){
      size_t row = base + it*64 + ty*8 + r;
      float4 o; o.x=qacc[r][0]; o.y=qacc[r][1]; o.z=qacc[r][2]; o.w=qacc[r][3];
      *(float4*)(g_quad + row*HIDW + et*128 + tx*4) = o;
    }
    if (it==0){
      #pragma unroll
      for (int r=0;r<8;r++){
        float4 o;
        o.x=kvacc[r][0]*(1.0f/256.0f); o.y=kvacc[r][1]*(1.0f/256.0f);
        o.z=kvacc[r][2]*(1.0f/256.0f); o.w=kvacc[r][3]*(1.0f/256.0f);
        *(float4*)(g_kv + ((size_t)(b*NG+g)*QKD + ty*8 + r)*HIDW + et*128 + tx*4) = o;
      }
    }
  }
}

// ---------------- exclusive cumsum of kv over groups (in place) ------------
__global__ void cumsum_kernel(){
  int b = blockIdx.y;
  int idx = blockIdx.x*256 + threadIdx.x;   // 0..32767 = d*512+e
  float acc = 0.f;
  #pragma unroll
  for (int g=0; g<NG; g++){
    size_t p = ((size_t)(b*NG+g))*(QKD*HIDW) + idx;
    float cur = g_kv[p];
    g_kv[p] = acc;
    acc += cur;
  }
}

// ---------------- linear attention + gated combine (writes bf16 splits) ----
#define LIN_SMEM ((64*64 + 64*128 + 128)*4)
__global__ void __launch_bounds__(256) lin_kernel(const float* __restrict__ gamma,
                                                  const float* __restrict__ beta){
  extern __shared__ float sm[];
  float* sLQ  = sm;              // [64][64]
  float* sLKV = sLQ + 64*64;     // [64][128]
  float* sG1  = sLKV + 64*128;   // [64]
  float* sB1  = sG1 + 64;        // [64]
  int et = blockIdx.x & 3, it = blockIdx.x >> 2;
  int g = blockIdx.y, b = blockIdx.z;
  int tid = threadIdx.x, ty = tid>>5, tx = tid&31;
  size_t base = (size_t)(b*NG+g)*GRP;

  if (tid < 64){ sG1[tid]=gamma[64+tid]; sB1[tid]=beta[64+tid]; }   // head 1 (lq)
  #pragma unroll
  for (int i=0;i<4;i++){
    int idx = i*256+tid; int r = idx>>4, c4 = (idx&15)*4;
    *(float4*)&sLQ[r*64+c4] = *(const float4*)(g_qk + (base + it*64 + r)*QKD + c4);
  }
  #pragma unroll
  for (int i=0;i<8;i++){
    int idx=i*256+tid; int r=idx>>5, c4=(idx&31)*4;
    *(float4*)&sLKV[r*128+c4] = *(const float4*)(g_kv + ((size_t)(b*NG+g)*QKD + r)*HIDW + et*128 + c4);
  }
  __syncthreads();
  #pragma unroll
  for (int i=0;i<16;i++){
    int idx=i*256+tid; int r=idx>>6, d=idx&63;
    sLQ[r*64+d] = fmaf(sLQ[r*64+d], sG1[d], sB1[d]);
  }
  __syncthreads();

  float acc[8][4];
  #pragma unroll
  for (int r=0;r<8;r++){ acc[r][0]=0.f; acc[r][1]=0.f; acc[r][2]=0.f; acc[r][3]=0.f; }
  #pragma unroll 4
  for (int d=0; d<64; d++){
    float4 kv4 = *(float4*)&sLKV[d*128 + tx*4];
    float a[8];
    #pragma unroll
    for (int r=0;r<8;r++) a[r] = sLQ[(ty*8+r)*64 + d];
    #pragma unroll
    for (int r=0;r<8;r++){
      acc[r][0]=fmaf(a[r],kv4.x,acc[r][0]);
      acc[r][1]=fmaf(a[r],kv4.y,acc[r][1]);
      acc[r][2]=fmaf(a[r],kv4.z,acc[r][2]);
      acc[r][3]=fmaf(a[r],kv4.w,acc[r][3]);
    }
  }
  #pragma unroll
  for (int r=0;r<8;r++){
    size_t row = base + it*64 + ty*8 + r;
    int e = et*128 + tx*4;
    float4 q  = *(float4*)(g_quad + row*HIDW + e);
    float4 gt = *(float4*)(g_hid + row*H2 + HIDW + e);
    float o[4];
    o[0] = gt.x*(q.x+acc[r][0]);
    o[1] = gt.y*(q.y+acc[r][1]);
    o[2] = gt.z*(q.z+acc[r][2]);
    o[3] = gt.w*(q.w+acc[r][3]);
    size_t p = row*HIDW + e;
    #pragma unroll
    for (int c=0;c<4;c++){
      __nv_bfloat16 h = __float2bfloat16(o[c]);
      g_aqh[p+c] = h;
      g_aql[p+c] = __float2bfloat16(o[c] - __bfloat162float(h));
    }
  }
}

// ---------------- final mean pool + classifier -----------------------------
__global__ void mean1_kernel(){
  int c = blockIdx.x, b = blockIdx.y, d = threadIdx.x;
  float s = 0.f;
  size_t rb = (size_t)b*8192 + (size_t)c*256;
  for (int r=0;r<256;r++) s += g_h[(rb+r)*DIM + d];
  g_part[(b*NG+c)*DIM + d] = s;
}

__global__ void head_kernel(const float* __restrict__ Wd, const float* __restrict__ bd,
                            float* __restrict__ out){
  int b = blockIdx.x, d = threadIdx.x;
  float s = 0.f;
  for (int c=0;c<NG;c++) s += g_part[(b*NG+c)*DIM + d];
  s *= (1.0f/8192.0f);
  __shared__ float r0[256], r1[256];
  r0[d] = s*Wd[d*2+0];
  r1[d] = s*Wd[d*2+1];
  __syncthreads();
  for (int o=128;o>0;o>>=1){
    if (d<o){ r0[d]+=r0[d+o]; r1[d]+=r1[d+o]; }
    __syncthreads();
  }
  if (d==0){ out[b*2+0]=r0[0]+bd[0]; out[b*2+1]=r1[0]+bd[1]; }
}

// ---------------- host ------------------------------------------------------
extern "C" void kernel_launch(void* const* d_in, const int* in_sizes, int n_in,
                              void* d_out, int out_size){
  const float* x      = (const float*)d_in[0];
  const float* W_emb  = (const float*)d_in[1];
  const float* b_emb  = (const float*)d_in[2];
  const float* pos    = (const float*)d_in[3];
  const float* ln_g   = (const float*)d_in[4];
  const float* ln_b   = (const float*)d_in[5];
  const float* Wh     = (const float*)d_in[6];
  const float* bh     = (const float*)d_in[7];
  const float* Wqk    = (const float*)d_in[8];
  const float* bqk    = (const float*)d_in[9];
  const float* gamma  = (const float*)d_in[10];
  const float* beta   = (const float*)d_in[11];
  const float* relb   = (const float*)d_in[12];
  const float* Wo     = (const float*)d_in[13];
  const float* bo     = (const float*)d_in[14];
  const float* Wd     = (const float*)d_in[15];
  const float* bd     = (const float*)d_in[16];
  float* out = (float*)d_out;

  cudaFuncSetAttribute(attn_kernel, cudaFuncAttributeMaxDynamicSharedMemorySize, ATTN_SMEM);
  cudaFuncSetAttribute(lin_kernel,  cudaFuncAttributeMaxDynamicSharedMemorySize, LIN_SMEM);
  cudaFuncSetAttribute(mma_gemm<0>, cudaFuncAttributeMaxDynamicSharedMemorySize, GSM);
  cudaFuncSetAttribute(mma_gemm<2>, cudaFuncAttributeMaxDynamicSharedMemorySize, GSM);

  // prologue: 3 launches so mma_gemm<0> is launch #3 (0-based) for ncu
  wprep_all<<<dim3(32, 16, NLAYER*3), dim3(32,8)>>>(Wh, Wqk, Wo);
  misc_prep<<<dim3(GRP, NLAYER), GRP>>>(relb, bh, bqk);
  embed_ln_kernel<<<TOK,256>>>(x, W_emb, b_emb, pos, ln_g, ln_b);

  for (int l=0;l<NLAYER;l++){
    int base = l*WLAYER;
    if (l > 0) ln_kernel<<<TOK,256>>>(ln_g + l*DIM, ln_b + l*DIM);
    mma_gemm<0><<<dim3(NCAT/64, TOK/128), 256, GSM>>>(base, nullptr, l);
    attn_kernel<<<dim3(4,NG,NBATCH),256,ATTN_SMEM>>>(gamma + l*256, beta + l*256, l);
    cumsum_kernel<<<dim3(128,NBATCH),256>>>();
    lin_kernel<<<dim3(16,NG,NBATCH),256,LIN_SMEM>>>(gamma + l*256, beta + l*256);
    mma_gemm<2><<<dim3(DIM/64, TOK/128), 256, GSM>>>(base + NCAT*DIM, bo + l*DIM, l);
  }
  mean1_kernel<<<dim3(NG,NBATCH),256>>>();
  head_kernel<<<NBATCH,256>>>(Wd, bd, out);
}

// round 14
// speedup vs baseline: 1.0430x; 1.0430x over previous
#include <cuda_runtime.h>
#include <cuda_bf16.h>
#include <math.h>
#include <stdint.h>

#define TOK 32768      // B*N = 4*8192
#define DIM 256
#define HIDW 512
#define H2 1024
#define QKD 64
#define NCAT (H2+QKD)  // 1088 combined gemm01 output width
#define GRP 256
#define NG 32          // groups per sequence
#define NBATCH 4
#define NLAYER 8
#define WLAYER (NCAT*DIM + HIDW*DIM)   // 409600
#define WTOT (NLAYER*WLAYER)

// ---------------- scratch (device globals only; no allocation) -------------
__device__ float g_h[TOK*DIM];
__device__ float g_hid[TOK*H2];
__device__ float g_qk[TOK*QKD];
__device__ float g_quad[TOK*HIDW];
__device__ float g_kv[NBATCH*NG*QKD*HIDW];
__device__ float g_bias8[NLAYER*GRP*GRP];
__device__ float g_bcat[NLAYER*NCAT];
__device__ float g_part[NBATCH*NG*DIM];
// pre-split bf16 operands
__device__ __nv_bfloat16 g_axh[TOK*DIM],  g_axl[TOK*DIM];    // ln output
__device__ __nv_bfloat16 g_aqh[TOK*HIDW], g_aql[TOK*HIDW];   // gated quad+lin
__device__ __nv_bfloat16 g_wh[WTOT], g_wl[WTOT];             // packed weights [n][k]

__device__ __forceinline__ float siluf(float x){ return x/(1.0f+expf(-x)); }

// ---------------- weight prep: ALL groups in one launch --------------------
__global__ void wprep_all(const float* __restrict__ Wh, const float* __restrict__ Wqk,
                          const float* __restrict__ Wo){
  int z = blockIdx.z;
  int l = z/3, grp = z - l*3;
  int K, N, dstBase;
  const float* W;
  if (grp == 0){ W = Wh  + (size_t)l*DIM*H2;   K = DIM;  N = H2;  dstBase = 0; }
  else if (grp == 1){ W = Wqk + (size_t)l*DIM*QKD; K = DIM;  N = QKD; dstBase = H2*DIM; }
  else { W = Wo  + (size_t)l*HIDW*DIM; K = HIDW; N = DIM; dstBase = NCAT*DIM; }
  int n0 = blockIdx.x*32, k0 = blockIdx.y*32;
  if (n0 >= N || k0 >= K) return;
  size_t dbase = (size_t)l*WLAYER + dstBase;
  __shared__ float t[32][33];
  int tx = threadIdx.x, ty = threadIdx.y;   // 32 x 8
  #pragma unroll
  for (int i=0;i<32;i+=8)
    t[ty+i][tx] = W[(size_t)(k0+ty+i)*N + n0+tx];
  __syncthreads();
  #pragma unroll
  for (int i=0;i<32;i+=8){
    float v = t[tx][ty+i];
    __nv_bfloat16 h = __float2bfloat16(v);
    float hf = __bfloat162float(h);
    size_t o = dbase + (size_t)(n0+ty+i)*K + k0+tx;
    g_wh[o] = h;
    g_wl[o] = __float2bfloat16(v - hf);
  }
}

// ---------------- misc prep: rel-pos bias tables + concat biases -----------
__global__ void misc_prep(const float* __restrict__ relb, const float* __restrict__ bh,
                          const float* __restrict__ bqk){
  int i = blockIdx.x, l = blockIdx.y, j = threadIdx.x;
  int n = i - j; if (n < 0) n = 0;
  int bucket;
  if (n < 16) bucket = n;
  else {
    float t = logf((float)n * (1.0f/16.0f)) * (16.0f / 2.0794415416798357f); // /log(8)
    int val = 16 + (int)t;
    bucket = val < 31 ? val : 31;
  }
  g_bias8[((size_t)l*GRP + i)*GRP + j] = relb[l*32 + bucket]*8.0f;   // * sqrt(QKD)
  int idx = i*GRP + j;
  if (idx < NCAT)
    g_bcat[l*NCAT + idx] = (idx < H2) ? bh[l*H2 + idx] : bqk[l*QKD + idx - H2];
}

// ---------------- fused embed + layer-0 layernorm --------------------------
__global__ void embed_ln_kernel(const float* __restrict__ x, const float* __restrict__ W,
                                const float* __restrict__ be, const float* __restrict__ pos,
                                const float* __restrict__ gl, const float* __restrict__ bl){
  int row = blockIdx.x;
  int n = row & 8191;
  int d = threadIdx.x;
  __shared__ float xs[8];
  __shared__ float red[8];
  if (d < 5) xs[d] = x[row*5+d];
  __syncthreads();
  float v = be[d] + pos[n*DIM+d];
  #pragma unroll
  for (int k=0;k<5;k++) v = fmaf(xs[k], W[k*DIM+d], v);
  g_h[row*DIM+d] = v;
  float s = v;
  #pragma unroll
  for (int o=16;o>0;o>>=1) s += __shfl_xor_sync(0xffffffffu, s, o);
  if ((d&31)==0) red[d>>5] = s;
  __syncthreads();
  float tot = 0.f;
  #pragma unroll
  for (int i=0;i<8;i++) tot += red[i];
  float mu = tot * (1.0f/DIM);
  float dv = v - mu;
  __syncthreads();
  float sq = dv*dv;
  #pragma unroll
  for (int o=16;o>0;o>>=1) sq += __shfl_xor_sync(0xffffffffu, sq, o);
  if ((d&31)==0) red[d>>5] = sq;
  __syncthreads();
  float vt = 0.f;
  #pragma unroll
  for (int i=0;i<8;i++) vt += red[i];
  float var = vt*(1.0f/DIM);
  float y = fmaf(dv*rsqrtf(var+1e-5f), gl[d], bl[d]);
  __nv_bfloat16 h = __float2bfloat16(y);
  g_axh[row*DIM+d] = h;
  g_axl[row*DIM+d] = __float2bfloat16(y - __bfloat162float(h));
}

// ---------------- layernorm (layers 1..7) ----------------------------------
__global__ void ln_kernel(const float* __restrict__ gl, const float* __restrict__ bl){
  int row = blockIdx.x, d = threadIdx.x;
  float v = g_h[row*DIM+d];
  __shared__ float red[8];
  float s = v;
  #pragma unroll
  for (int o=16;o>0;o>>=1) s += __shfl_xor_sync(0xffffffffu, s, o);
  if ((d&31)==0) red[d>>5] = s;
  __syncthreads();
  float tot = 0.f;
  #pragma unroll
  for (int i=0;i<8;i++) tot += red[i];
  float mu = tot * (1.0f/DIM);
  float dv = v - mu;
  __syncthreads();
  float sq = dv*dv;
  #pragma unroll
  for (int o=16;o>0;o>>=1) sq += __shfl_xor_sync(0xffffffffu, sq, o);
  if ((d&31)==0) red[d>>5] = sq;
  __syncthreads();
  float vt = 0.f;
  #pragma unroll
  for (int i=0;i<8;i++) vt += red[i];
  float var = vt*(1.0f/DIM);
  float y = fmaf(dv*rsqrtf(var+1e-5f), gl[d], bl[d]);
  __nv_bfloat16 h = __float2bfloat16(y);
  g_axh[row*DIM+d] = h;
  g_axl[row*DIM+d] = __float2bfloat16(y - __bfloat162float(h));
}

// ---------------- split-bf16 tensor-core GEMM (k-tile 32, 2 CTA/SM) --------
// MODE 0: [hid|qk] = silu(nx @ [Wh|Wqk] + bcat)  [32768,256]x[256,1088]
// MODE 2: g_h  += quad @ Wo + bo                 [32768,512]x[512,256]
#define ABUF 2560   // 128*20 u32
#define BBUF 1280   // 64*20 u32
#define GSM ((2*ABUF*2 + 2*BBUF*2)*4)  // 61440 bytes

#define BMMA(acc, a, b0, b1) \
  asm volatile("mma.sync.aligned.m16n8k16.row.col.f32.bf16.bf16.f32 " \
    "{%0,%1,%2,%3}, {%4,%5,%6,%7}, {%8,%9}, {%0,%1,%2,%3};\n" \
    : "+f"(acc[0]),"+f"(acc[1]),"+f"(acc[2]),"+f"(acc[3]) \
    : "r"(a[0]),"r"(a[1]),"r"(a[2]),"r"(a[3]), "r"(b0),"r"(b1))

#define LDSM4(d0,d1,d2,d3,a) \
  asm volatile("ldmatrix.sync.aligned.m8n8.x4.shared.b16 {%0,%1,%2,%3}, [%4];" \
    : "=r"(d0),"=r"(d1),"=r"(d2),"=r"(d3) : "r"(a))

#define LDTILE(kt) do{ \
  size_t ko = (size_t)(kt)*32 + ac; \
  pah[0] = *(const uint4*)(Ah + (size_t)(m0+ar0)*K + ko); \
  pal[0] = *(const uint4*)(Al + (size_t)(m0+ar0)*K + ko); \
  pah[1] = *(const uint4*)(Ah + (size_t)(m0+ar0+64)*K + ko); \
  pal[1] = *(const uint4*)(Al + (size_t)(m0+ar0+64)*K + ko); \
  pbh    = *(const uint4*)(Bh_ + (size_t)(n0+ar0)*K + ko); \
  pbl    = *(const uint4*)(Bl_ + (size_t)(n0+ar0)*K + ko); \
}while(0)

#define STTILE(buf) do{ \
  *(uint4*)&AH[(buf)*ABUF + ar0*20 + acu] = pah[0]; \
  *(uint4*)&AL[(buf)*ABUF + ar0*20 + acu] = pal[0]; \
  *(uint4*)&AH[(buf)*ABUF + (ar0+64)*20 + acu] = pah[1]; \
  *(uint4*)&AL[(buf)*ABUF + (ar0+64)*20 + acu] = pal[1]; \
  *(uint4*)&BH[(buf)*BBUF + ar0*20 + acu] = pbh; \
  *(uint4*)&BL[(buf)*BBUF + ar0*20 + acu] = pbl; \
}while(0)

template<int MODE>
__global__ void __launch_bounds__(256) mma_gemm(int woff, const float* __restrict__ bias_p,
                                                int lay){
  constexpr int K  = (MODE==2)?HIDW:DIM;
  constexpr int KT = K/32;

  const __nv_bfloat16* Ah = (MODE==2)? g_aqh : g_axh;
  const __nv_bfloat16* Al = (MODE==2)? g_aql : g_axl;
  const __nv_bfloat16* Bh_ = g_wh + woff;
  const __nv_bfloat16* Bl_ = g_wl + woff;
  const float* bias = (MODE==0) ? (g_bcat + lay*NCAT) : bias_p;

  extern __shared__ uint32_t smu[];
  uint32_t* AH = smu;
  uint32_t* AL = smu + 2*ABUF;
  uint32_t* BH = smu + 4*ABUF;
  uint32_t* BL = smu + 4*ABUF + 2*BBUF;
  uint32_t smb = (uint32_t)__cvta_generic_to_shared(smu);

  int tid = threadIdx.x;
  int warp = tid>>5, lane = tid&31;
  int gq = lane>>2, tig = lane&3;
  int wm = (warp>>1)*32, wn = (warp&1)*32;
  int m0 = blockIdx.y*128, n0 = blockIdx.x*64;

  int ar0 = tid>>2;            // A rows ar0, ar0+64; B row ar0 (0..63)
  int ac  = (tid&3)*8;         // bf16 col within k-tile
  int acu = (tid&3)*4;         // u32 col

  int lg = lane>>3, lr = lane&7;
  uint32_t aoff[2], boff[2];
  #pragma unroll
  for (int mt=0;mt<2;mt++)
    aoff[mt] = (uint32_t)((wm + mt*16 + (lg&1)*8 + lr)*20 + (lg>>1)*4);
  #pragma unroll
  for (int p=0;p<2;p++)
    boff[p] = (uint32_t)((wn + p*16 + (lg>>1)*8 + lr)*20 + (lg&1)*4);

  float acc[2][4][4];
  #pragma unroll
  for (int mt=0;mt<2;mt++)
    #pragma unroll
    for (int nt=0;nt<4;nt++)
      #pragma unroll
      for (int c=0;c<4;c++) acc[mt][nt][c]=0.f;

  uint4 pah[2], pal[2], pbh, pbl;

  LDTILE(0);
  STTILE(0);
  __syncthreads();

  for (int kt=0; kt<KT; kt++){
    int buf = kt&1;
    if (kt+1 < KT) LDTILE(kt+1);

    uint32_t abase  = smb + (buf*ABUF)*4;
    uint32_t albase = smb + ((2+buf)*ABUF)*4;
    uint32_t bbase  = smb + (4*ABUF + buf*BBUF)*4;
    uint32_t blbase = smb + (4*ABUF + (2+buf)*BBUF)*4;

    #pragma unroll
    for (int kk=0;kk<2;kk++){
      uint32_t ah[2][4], al[2][4];
      #pragma unroll
      for (int mt=0;mt<2;mt++){
        LDSM4(ah[mt][0],ah[mt][1],ah[mt][2],ah[mt][3], abase  + (aoff[mt] + kk*8)*4);
        LDSM4(al[mt][0],al[mt][1],al[mt][2],al[mt][3], albase + (aoff[mt] + kk*8)*4);
      }
      uint32_t bh[2][4], bl[2][4];
      #pragma unroll
      for (int p=0;p<2;p++){
        LDSM4(bh[p][0],bh[p][1],bh[p][2],bh[p][3], bbase  + (boff[p] + kk*8)*4);
        LDSM4(bl[p][0],bl[p][1],bl[p][2],bl[p][3], blbase + (boff[p] + kk*8)*4);
      }
      #pragma unroll
      for (int mt=0;mt<2;mt++)
        #pragma unroll
        for (int p=0;p<2;p++)
          #pragma unroll
          for (int h=0;h<2;h++){
            float* a4 = acc[mt][p*2+h];
            BMMA(a4, ah[mt], bh[p][h*2], bh[p][h*2+1]);
            BMMA(a4, ah[mt], bl[p][h*2], bl[p][h*2+1]);
            BMMA(a4, al[mt], bh[p][h*2], bh[p][h*2+1]);
          }
    }
    if (kt+1 < KT) STTILE(buf^1);
    __syncthreads();
  }

  // epilogue
  bool isqk = (MODE==0) && (n0 >= H2);
  #pragma unroll
  for (int mt=0;mt<2;mt++){
    int r0 = m0 + wm + mt*16 + gq;
    #pragma unroll
    for (int nt=0;nt<4;nt++){
      int c0 = n0 + wn + nt*8 + tig*2;
      float b0 = bias[c0], b1 = bias[c0+1];
      #pragma unroll
      for (int h=0;h<2;h++){
        int row = r0 + h*8;
        float v0 = acc[mt][nt][h*2+0] + b0;
        float v1 = acc[mt][nt][h*2+1] + b1;
        if (MODE==2){
          float* p = g_h + (size_t)row*DIM + c0;
          p[0] += v0; p[1] += v1;
        } else if (isqk){
          float* p = g_qk + (size_t)row*QKD + (c0 - H2);
          p[0] = siluf(v0); p[1] = siluf(v1);
        } else {
          float* p = g_hid + (size_t)row*H2 + c0;
          p[0] = siluf(v0); p[1] = siluf(v1);
        }
      }
    }
  }
}

// ---------------- fused quad attention + K^T V -----------------------------
// sAtt stored TRANSPOSED [j][i] (stride 68) for vectorized phase-B loads.
#define SQS 68
#define SAI 68
#define ATTN_SMEM ((256*SQS + 64*SQS + 256*SAI + 64*128 + 6*64)*4)

__global__ void __launch_bounds__(256) attn_kernel(const float* __restrict__ gamma,
                                                   const float* __restrict__ beta,
                                                   int lay){
  extern __shared__ float sm[];
  float* sQK  = sm;                 // [256][68]  raw silu(qk)
  float* sQQ  = sQK + 256*SQS;      // [64][68]   quad queries (this i-tile)
  float* sAtt = sQQ + 64*SQS;       // [256 j][68 i] laplace attn (transposed)
  float* sV   = sAtt + 256*SAI;     // [64][128]  v chunk
  float* sG   = sV + 64*128;        // g0,b0,g2,b2,g3,b3 (6*64)
  int it = blockIdx.x, g = blockIdx.y, b = blockIdx.z;
  int tid = threadIdx.x;
  size_t base = (size_t)(b*NG + g)*GRP;
  const float* btab = g_bias8 + (size_t)lay*GRP*GRP;

  #pragma unroll
  for (int i=0;i<16;i++){
    int idx = i*256+tid;
    int r = idx>>4, c4 = (idx&15)*4;
    *(float4*)&sQK[r*SQS + c4] = *(const float4*)(g_qk + (base+r)*QKD + c4);
  }
  if (tid < 64){
    sG[tid]     = gamma[tid];      sG[64+tid]  = beta[tid];        // head 0 (qq)
    sG[128+tid] = gamma[128+tid];  sG[192+tid] = beta[128+tid];    // head 2 (qk)
    sG[256+tid] = gamma[192+tid];  sG[320+tid] = beta[192+tid];    // head 3 (lk)
  }
  __syncthreads();
  #pragma unroll
  for (int i=0;i<16;i++){
    int idx = i*256+tid; int ii = idx>>6, d = idx&63;
    sQQ[ii*SQS+d] = fmaf(sQK[(it*64+ii)*SQS + d], sG[d], sG[64+d]);
  }
  __syncthreads();

  int ty = tid>>5, tx = tid&31;
  // phase A: sim = qq.qkk/256 + bias -> laplace -> causal mask -> sAtt[j][i]
  {
    float acc[8][8];
    #pragma unroll
    for (int r=0;r<8;r++)
      #pragma unroll
      for (int c=0;c<8;c++) acc[r][c]=0.f;
    #pragma unroll 4
    for (int d=0; d<64; d++){
      float g2 = sG[128+d], b2 = sG[192+d];
      float a[8], kk[8];
      #pragma unroll
      for (int r=0;r<8;r++) a[r] = sQQ[(ty*8+r)*SQS + d];
      #pragma unroll
      for (int c=0;c<8;c++) kk[c] = fmaf(sQK[(tx + 32*c)*SQS + d], g2, b2);
      #pragma unroll
      for (int r=0;r<8;r++)
        #pragma unroll
        for (int c=0;c<8;c++) acc[r][c] = fmaf(a[r], kk[c], acc[r][c]);
    }
    #pragma unroll
    for (int c=0;c<8;c++){
      int j = tx + 32*c;
      float tmp[8];
      #pragma unroll
      for (int r=0;r<8;r++){
        int ig = it*64 + ty*8 + r;
        float s = acc[r][c]*(1.0f/256.0f) + btab[ig*GRP + j];
        tmp[r] = (j <= ig) ? 0.5f*(1.0f + erff((s - 0.70710678f)*0.79788456f)) : 0.0f;
      }
      *(float4*)&sAtt[j*SAI + ty*8]     = *(float4*)&tmp[0];
      *(float4*)&sAtt[j*SAI + ty*8 + 4] = *(float4*)&tmp[4];
    }
  }

  float g3r[8], b3r[8];
  #pragma unroll
  for (int r=0;r<8;r++){ g3r[r]=sG[256+ty*8+r]; b3r[r]=sG[320+ty*8+r]; }

  // phase B: quad = attn @ v, plus (it==0) kv = lk^T v / 256
  for (int et=0; et<4; et++){
    float qacc[8][4], kvacc[8][4];
    #pragma unroll
    for (int r=0;r<8;r++)
      #pragma unroll
      for (int c=0;c<4;c++){ qacc[r][c]=0.f; kvacc[r][c]=0.f; }
    for (int jc=0;jc<4;jc++){
      __syncthreads();
      #pragma unroll
      for (int i=0;i<8;i++){
        int idx = i*256+tid;
        int r = idx>>5, c4 = (idx&31)*4;
        *(float4*)&sV[r*128+c4] = *(const float4*)(g_hid + (base + jc*64 + r)*H2 + et*128 + c4);
      }
      __syncthreads();
      #pragma unroll 2
      for (int jj=0;jj<64;jj++){
        int j = jc*64 + jj;
        float4 v4 = *(float4*)&sV[jj*128 + tx*4];
        float4 a0 = *(float4*)&sAtt[j*SAI + ty*8];
        float4 a1 = *(float4*)&sAtt[j*SAI + ty*8 + 4];
        float a[8] = {a0.x,a0.y,a0.z,a0.w,a1.x,a1.y,a1.z,a1.w};
        #pragma unroll
        for (int r=0;r<8;r++){
          qacc[r][0]=fmaf(a[r],v4.x,qacc[r][0]);
          qacc[r][1]=fmaf(a[r],v4.y,qacc[r][1]);
          qacc[r][2]=fmaf(a[r],v4.z,qacc[r][2]);
          qacc[r][3]=fmaf(a[r],v4.w,qacc[r][3]);
        }
        if (it==0){
          float4 q0 = *(float4*)&sQK[j*SQS + ty*8];
          float4 q1 = *(float4*)&sQK[j*SQS + ty*8 + 4];
          float qv[8] = {q0.x,q0.y,q0.z,q0.w,q1.x,q1.y,q1.z,q1.w};
          #pragma unroll
          for (int r=0;r<8;r++){
            float lk = fmaf(qv[r], g3r[r], b3r[r]);
            kvacc[r][0]=fmaf(lk,v4.x,kvacc[r][0]);
            kvacc[r][1]=fmaf(lk,v4.y,kvacc[r][1]);
            kvacc[r][2]=fmaf(lk,v4.z,kvacc[r][2]);
            kvacc[r][3]=fmaf(lk,v4.w,kvacc[r][3]);
          }
        }
      }
    }
    #pragma unroll
    for (int r=0;r<8;r++){
      size_t row = base + it*64 + ty*8 + r;
      float4 o; o.x=qacc[r][0]; o.y=qacc[r][1]; o.z=qacc[r][2]; o.w=qacc[r][3];
      *(float4*)(g_quad + row*HIDW + et*128 + tx*4) = o;
    }
    if (it==0){
      #pragma unroll
      for (int r=0;r<8;r++){
        float4 o;
        o.x=kvacc[r][0]*(1.0f/256.0f); o.y=kvacc[r][1]*(1.0f/256.0f);
        o.z=kvacc[r][2]*(1.0f/256.0f); o.w=kvacc[r][3]*(1.0f/256.0f);
        *(float4*)(g_kv + ((size_t)(b*NG+g)*QKD + ty*8 + r)*HIDW + et*128 + tx*4) = o;
      }
    }
  }
}

// ---------------- exclusive cumsum of kv over groups (in place) ------------
__global__ void cumsum_kernel(){
  int b = blockIdx.y;
  int idx = blockIdx.x*256 + threadIdx.x;   // 0..32767 = d*512+e
  float acc = 0.f;
  #pragma unroll
  for (int g=0; g<NG; g++){
    size_t p = ((size_t)(b*NG+g))*(QKD*HIDW) + idx;
    float cur = g_kv[p];
    g_kv[p] = acc;
    acc += cur;
  }
}

// ---------------- linear attention + gated combine (writes bf16 splits) ----
#define LIN_SMEM ((64*64 + 64*128 + 128)*4)
__global__ void __launch_bounds__(256) lin_kernel(const float* __restrict__ gamma,
                                                  const float* __restrict__ beta){
  extern __shared__ float sm[];
  float* sLQ  = sm;              // [64][64]
  float* sLKV = sLQ + 64*64;     // [64][128]
  float* sG1  = sLKV + 64*128;   // [64]
  float* sB1  = sG1 + 64;        // [64]
  int et = blockIdx.x & 3, it = blockIdx.x >> 2;
  int g = blockIdx.y, b = blockIdx.z;
  int tid = threadIdx.x, ty = tid>>5, tx = tid&31;
  size_t base = (size_t)(b*NG+g)*GRP;

  if (tid < 64){ sG1[tid]=gamma[64+tid]; sB1[tid]=beta[64+tid]; }   // head 1 (lq)
  #pragma unroll
  for (int i=0;i<4;i++){
    int idx = i*256+tid; int r = idx>>4, c4 = (idx&15)*4;
    *(float4*)&sLQ[r*64+c4] = *(const float4*)(g_qk + (base + it*64 + r)*QKD + c4);
  }
  #pragma unroll
  for (int i=0;i<8;i++){
    int idx=i*256+tid; int r=idx>>5, c4=(idx&31)*4;
    *(float4*)&sLKV[r*128+c4] = *(const float4*)(g_kv + ((size_t)(b*NG+g)*QKD + r)*HIDW + et*128 + c4);
  }
  __syncthreads();
  #pragma unroll
  for (int i=0;i<16;i++){
    int idx=i*256+tid; int r=idx>>6, d=idx&63;
    sLQ[r*64+d] = fmaf(sLQ[r*64+d], sG1[d], sB1[d]);
  }
  __syncthreads();

  float acc[8][4];
  #pragma unroll
  for (int r=0;r<8;r++){ acc[r][0]=0.f; acc[r][1]=0.f; acc[r][2]=0.f; acc[r][3]=0.f; }
  #pragma unroll 4
  for (int d=0; d<64; d++){
    float4 kv4 = *(float4*)&sLKV[d*128 + tx*4];
    float a[8];
    #pragma unroll
    for (int r=0;r<8;r++) a[r] = sLQ[(ty*8+r)*64 + d];
    #pragma unroll
    for (int r=0;r<8;r++){
      acc[r][0]=fmaf(a[r],kv4.x,acc[r][0]);
      acc[r][1]=fmaf(a[r],kv4.y,acc[r][1]);
      acc[r][2]=fmaf(a[r],kv4.z,acc[r][2]);
      acc[r][3]=fmaf(a[r],kv4.w,acc[r][3]);
    }
  }
  #pragma unroll
  for (int r=0;r<8;r++){
    size_t row = base + it*64 + ty*8 + r;
    int e = et*128 + tx*4;
    float4 q  = *(float4*)(g_quad + row*HIDW + e);
    float4 gt = *(float4*)(g_hid + row*H2 + HIDW + e);
    float o[4];
    o[0] = gt.x*(q.x+acc[r][0]);
    o[1] = gt.y*(q.y+acc[r][1]);
    o[2] = gt.z*(q.z+acc[r][2]);
    o[3] = gt.w*(q.w+acc[r][3]);
    size_t p = row*HIDW + e;
    #pragma unroll
    for (int c=0;c<4;c++){
      __nv_bfloat16 h = __float2bfloat16(o[c]);
      g_aqh[p+c] = h;
      g_aql[p+c] = __float2bfloat16(o[c] - __bfloat162float(h));
    }
  }
}

// ---------------- final mean pool + classifier -----------------------------
__global__ void mean1_kernel(){
  int c = blockIdx.x, b = blockIdx.y, d = threadIdx.x;
  float s = 0.f;
  size_t rb = (size_t)b*8192 + (size_t)c*256;
  for (int r=0;r<256;r++) s += g_h[(rb+r)*DIM + d];
  g_part[(b*NG+c)*DIM + d] = s;
}

__global__ void head_kernel(const float* __restrict__ Wd, const float* __restrict__ bd,
                            float* __restrict__ out){
  int b = blockIdx.x, d = threadIdx.x;
  float s = 0.f;
  for (int c=0;c<NG;c++) s += g_part[(b*NG+c)*DIM + d];
  s *= (1.0f/8192.0f);
  __shared__ float r0[256], r1[256];
  r0[d] = s*Wd[d*2+0];
  r1[d] = s*Wd[d*2+1];
  __syncthreads();
  for (int o=128;o>0;o>>=1){
    if (d<o){ r0[d]+=r0[d+o]; r1[d]+=r1[d+o]; }
    __syncthreads();
  }
  if (d==0){ out[b*2+0]=r0[0]+bd[0]; out[b*2+1]=r1[0]+bd[1]; }
}

// ---------------- host ------------------------------------------------------
extern "C" void kernel_launch(void* const* d_in, const int* in_sizes, int n_in,
                              void* d_out, int out_size){
  const float* x      = (const float*)d_in[0];
  const float* W_emb  = (const float*)d_in[1];
  const float* b_emb  = (const float*)d_in[2];
  const float* pos    = (const float*)d_in[3];
  const float* ln_g   = (const float*)d_in[4];
  const float* ln_b   = (const float*)d_in[5];
  const float* Wh     = (const float*)d_in[6];
  const float* bh     = (const float*)d_in[7];
  const float* Wqk    = (const float*)d_in[8];
  const float* bqk    = (const float*)d_in[9];
  const float* gamma  = (const float*)d_in[10];
  const float* beta   = (const float*)d_in[11];
  const float* relb   = (const float*)d_in[12];
  const float* Wo     = (const float*)d_in[13];
  const float* bo     = (const float*)d_in[14];
  const float* Wd     = (const float*)d_in[15];
  const float* bd     = (const float*)d_in[16];
  float* out = (float*)d_out;

  cudaFuncSetAttribute(attn_kernel, cudaFuncAttributeMaxDynamicSharedMemorySize, ATTN_SMEM);
  cudaFuncSetAttribute(lin_kernel,  cudaFuncAttributeMaxDynamicSharedMemorySize, LIN_SMEM);
  cudaFuncSetAttribute(mma_gemm<0>, cudaFuncAttributeMaxDynamicSharedMemorySize, GSM);
  cudaFuncSetAttribute(mma_gemm<2>, cudaFuncAttributeMaxDynamicSharedMemorySize, GSM);

  // prologue: 3 launches so mma_gemm<0> is launch #3 (0-based) for ncu
  wprep_all<<<dim3(32, 16, NLAYER*3), dim3(32,8)>>>(Wh, Wqk, Wo);
  misc_prep<<<dim3(GRP, NLAYER), GRP>>>(relb, bh, bqk);
  embed_ln_kernel<<<TOK,256>>>(x, W_emb, b_emb, pos, ln_g, ln_b);

  for (int l=0;l<NLAYER;l++){
    int base = l*WLAYER;
    if (l > 0) ln_kernel<<<TOK,256>>>(ln_g + l*DIM, ln_b + l*DIM);
    mma_gemm<0><<<dim3(NCAT/64, TOK/128), 256, GSM>>>(base, nullptr, l);
    attn_kernel<<<dim3(4,NG,NBATCH),256,ATTN_SMEM>>>(gamma + l*256, beta + l*256, l);
    cumsum_kernel<<<dim3(128,NBATCH),256>>>();
    lin_kernel<<<dim3(16,NG,NBATCH),256,LIN_SMEM>>>(gamma + l*256, beta + l*256);
    mma_gemm<2><<<dim3(DIM/64, TOK/128), 256, GSM>>>(base + NCAT*DIM, bo + l*DIM, l);
  }
  mean1_kernel<<<dim3(NG,NBATCH),256>>>();
  head_kernel<<<NBATCH,256>>>(Wd, bd, out);
}

// round 15
// speedup vs baseline: 1.2446x; 1.1933x over previous
#include <cuda_runtime.h>
#include <cuda_bf16.h>
#include <math.h>
#include <stdint.h>

#define TOK 32768      // B*N = 4*8192
#define DIM 256
#define HIDW 512
#define H2 1024
#define QKD 64
#define NCAT (H2+QKD)  // 1088 combined gemm01 output width
#define GRP 256
#define NG 32          // groups per sequence
#define NBATCH 4
#define NLAYER 8
#define WLAYER (NCAT*DIM + HIDW*DIM)   // 409600
#define WTOT (NLAYER*WLAYER)

// ---------------- scratch (device globals only; no allocation) -------------
__device__ float g_h[TOK*DIM];
__device__ float g_hid[TOK*H2];
__device__ float g_qk[TOK*QKD];
__device__ float g_quad[TOK*HIDW];
__device__ float g_kv[NBATCH*NG*QKD*HIDW];
__device__ float g_bias8[NLAYER*GRP*GRP];
__device__ float g_bcat[NLAYER*NCAT];
__device__ float g_part[NBATCH*NG*DIM];
// pre-split bf16 operands
__device__ __nv_bfloat16 g_axh[TOK*DIM],  g_axl[TOK*DIM];    // ln output
__device__ __nv_bfloat16 g_aqh[TOK*HIDW], g_aql[TOK*HIDW];   // gated quad+lin
__device__ __nv_bfloat16 g_wh[WTOT], g_wl[WTOT];             // packed weights [n][k]

__device__ __forceinline__ float siluf(float x){ return x/(1.0f+expf(-x)); }
__device__ __forceinline__ uint32_t bpack(float lo, float hi){
  uint32_t r; asm("cvt.rn.bf16x2.f32 %0, %1, %2;" : "=r"(r) : "f"(hi), "f"(lo));
  return r;
}

// ---------------- weight prep: ALL groups in one launch --------------------
__global__ void wprep_all(const float* __restrict__ Wh, const float* __restrict__ Wqk,
                          const float* __restrict__ Wo){
  int z = blockIdx.z;
  int l = z/3, grp = z - l*3;
  int K, N, dstBase;
  const float* W;
  if (grp == 0){ W = Wh  + (size_t)l*DIM*H2;   K = DIM;  N = H2;  dstBase = 0; }
  else if (grp == 1){ W = Wqk + (size_t)l*DIM*QKD; K = DIM;  N = QKD; dstBase = H2*DIM; }
  else { W = Wo  + (size_t)l*HIDW*DIM; K = HIDW; N = DIM; dstBase = NCAT*DIM; }
  int n0 = blockIdx.x*32, k0 = blockIdx.y*32;
  if (n0 >= N || k0 >= K) return;
  size_t dbase = (size_t)l*WLAYER + dstBase;
  __shared__ float t[32][33];
  int tx = threadIdx.x, ty = threadIdx.y;   // 32 x 8
  #pragma unroll
  for (int i=0;i<32;i+=8)
    t[ty+i][tx] = W[(size_t)(k0+ty+i)*N + n0+tx];
  __syncthreads();
  #pragma unroll
  for (int i=0;i<32;i+=8){
    float v = t[tx][ty+i];
    __nv_bfloat16 h = __float2bfloat16(v);
    float hf = __bfloat162float(h);
    size_t o = dbase + (size_t)(n0+ty+i)*K + k0+tx;
    g_wh[o] = h;
    g_wl[o] = __float2bfloat16(v - hf);
  }
}

// ---------------- misc prep: rel-pos bias tables + concat biases -----------
__global__ void misc_prep(const float* __restrict__ relb, const float* __restrict__ bh,
                          const float* __restrict__ bqk){
  int i = blockIdx.x, l = blockIdx.y, j = threadIdx.x;
  int n = i - j; if (n < 0) n = 0;
  int bucket;
  if (n < 16) bucket = n;
  else {
    float t = logf((float)n * (1.0f/16.0f)) * (16.0f / 2.0794415416798357f); // /log(8)
    int val = 16 + (int)t;
    bucket = val < 31 ? val : 31;
  }
  g_bias8[((size_t)l*GRP + i)*GRP + j] = relb[l*32 + bucket]*8.0f;   // * sqrt(QKD)
  int idx = i*GRP + j;
  if (idx < NCAT)
    g_bcat[l*NCAT + idx] = (idx < H2) ? bh[l*H2 + idx] : bqk[l*QKD + idx - H2];
}

// ---------------- fused embed + layer-0 layernorm --------------------------
__global__ void embed_ln_kernel(const float* __restrict__ x, const float* __restrict__ W,
                                const float* __restrict__ be, const float* __restrict__ pos,
                                const float* __restrict__ gl, const float* __restrict__ bl){
  int row = blockIdx.x;
  int n = row & 8191;
  int d = threadIdx.x;
  __shared__ float xs[8];
  __shared__ float red[8];
  if (d < 5) xs[d] = x[row*5+d];
  __syncthreads();
  float v = be[d] + pos[n*DIM+d];
  #pragma unroll
  for (int k=0;k<5;k++) v = fmaf(xs[k], W[k*DIM+d], v);
  g_h[row*DIM+d] = v;
  float s = v;
  #pragma unroll
  for (int o=16;o>0;o>>=1) s += __shfl_xor_sync(0xffffffffu, s, o);
  if ((d&31)==0) red[d>>5] = s;
  __syncthreads();
  float tot = 0.f;
  #pragma unroll
  for (int i=0;i<8;i++) tot += red[i];
  float mu = tot * (1.0f/DIM);
  float dv = v - mu;
  __syncthreads();
  float sq = dv*dv;
  #pragma unroll
  for (int o=16;o>0;o>>=1) sq += __shfl_xor_sync(0xffffffffu, sq, o);
  if ((d&31)==0) red[d>>5] = sq;
  __syncthreads();
  float vt = 0.f;
  #pragma unroll
  for (int i=0;i<8;i++) vt += red[i];
  float var = vt*(1.0f/DIM);
  float y = fmaf(dv*rsqrtf(var+1e-5f), gl[d], bl[d]);
  __nv_bfloat16 h = __float2bfloat16(y);
  g_axh[row*DIM+d] = h;
  g_axl[row*DIM+d] = __float2bfloat16(y - __bfloat162float(h));
}

// ---------------- layernorm (layers 1..7) ----------------------------------
__global__ void ln_kernel(const float* __restrict__ gl, const float* __restrict__ bl){
  int row = blockIdx.x, d = threadIdx.x;
  float v = g_h[row*DIM+d];
  __shared__ float red[8];
  float s = v;
  #pragma unroll
  for (int o=16;o>0;o>>=1) s += __shfl_xor_sync(0xffffffffu, s, o);
  if ((d&31)==0) red[d>>5] = s;
  __syncthreads();
  float tot = 0.f;
  #pragma unroll
  for (int i=0;i<8;i++) tot += red[i];
  float mu = tot * (1.0f/DIM);
  float dv = v - mu;
  __syncthreads();
  float sq = dv*dv;
  #pragma unroll
  for (int o=16;o>0;o>>=1) sq += __shfl_xor_sync(0xffffffffu, sq, o);
  if ((d&31)==0) red[d>>5] = sq;
  __syncthreads();
  float vt = 0.f;
  #pragma unroll
  for (int i=0;i<8;i++) vt += red[i];
  float var = vt*(1.0f/DIM);
  float y = fmaf(dv*rsqrtf(var+1e-5f), gl[d], bl[d]);
  __nv_bfloat16 h = __float2bfloat16(y);
  g_axh[row*DIM+d] = h;
  g_axl[row*DIM+d] = __float2bfloat16(y - __bfloat162float(h));
}

// ---------------- split-bf16 tensor-core GEMM (k-tile 32, 2 CTA/SM) --------
#define ABUF 2560   // 128*20 u32
#define BBUF 1280   // 64*20 u32
#define GSM ((2*ABUF*2 + 2*BBUF*2)*4)  // 61440 bytes

#define BMMA(acc, a, b0, b1) \
  asm volatile("mma.sync.aligned.m16n8k16.row.col.f32.bf16.bf16.f32 " \
    "{%0,%1,%2,%3}, {%4,%5,%6,%7}, {%8,%9}, {%0,%1,%2,%3};\n" \
    : "+f"(acc[0]),"+f"(acc[1]),"+f"(acc[2]),"+f"(acc[3]) \
    : "r"(a[0]),"r"(a[1]),"r"(a[2]),"r"(a[3]), "r"(b0),"r"(b1))

#define LDSM4(d0,d1,d2,d3,a) \
  asm volatile("ldmatrix.sync.aligned.m8n8.x4.shared.b16 {%0,%1,%2,%3}, [%4];" \
    : "=r"(d0),"=r"(d1),"=r"(d2),"=r"(d3) : "r"(a))

#define LDSM4T(d0,d1,d2,d3,a) \
  asm volatile("ldmatrix.sync.aligned.m8n8.x4.trans.shared.b16 {%0,%1,%2,%3}, [%4];" \
    : "=r"(d0),"=r"(d1),"=r"(d2),"=r"(d3) : "r"(a))

#define LDTILE(kt) do{ \
  size_t ko = (size_t)(kt)*32 + ac; \
  pah[0] = *(const uint4*)(Ah + (size_t)(m0+ar0)*K + ko); \
  pal[0] = *(const uint4*)(Al + (size_t)(m0+ar0)*K + ko); \
  pah[1] = *(const uint4*)(Ah + (size_t)(m0+ar0+64)*K + ko); \
  pal[1] = *(const uint4*)(Al + (size_t)(m0+ar0+64)*K + ko); \
  pbh    = *(const uint4*)(Bh_ + (size_t)(n0+ar0)*K + ko); \
  pbl    = *(const uint4*)(Bl_ + (size_t)(n0+ar0)*K + ko); \
}while(0)

#define STTILE(buf) do{ \
  *(uint4*)&AH[(buf)*ABUF + ar0*20 + acu] = pah[0]; \
  *(uint4*)&AL[(buf)*ABUF + ar0*20 + acu] = pal[0]; \
  *(uint4*)&AH[(buf)*ABUF + (ar0+64)*20 + acu] = pah[1]; \
  *(uint4*)&AL[(buf)*ABUF + (ar0+64)*20 + acu] = pal[1]; \
  *(uint4*)&BH[(buf)*BBUF + ar0*20 + acu] = pbh; \
  *(uint4*)&BL[(buf)*BBUF + ar0*20 + acu] = pbl; \
}while(0)

template<int MODE>
__global__ void __launch_bounds__(256) mma_gemm(int woff, const float* __restrict__ bias_p,
                                                int lay){
  constexpr int K  = (MODE==2)?HIDW:DIM;
  constexpr int KT = K/32;

  const __nv_bfloat16* Ah = (MODE==2)? g_aqh : g_axh;
  const __nv_bfloat16* Al = (MODE==2)? g_aql : g_axl;
  const __nv_bfloat16* Bh_ = g_wh + woff;
  const __nv_bfloat16* Bl_ = g_wl + woff;
  const float* bias = (MODE==0) ? (g_bcat + lay*NCAT) : bias_p;

  extern __shared__ uint32_t smu[];
  uint32_t* AH = smu;
  uint32_t* AL = smu + 2*ABUF;
  uint32_t* BH = smu + 4*ABUF;
  uint32_t* BL = smu + 4*ABUF + 2*BBUF;
  uint32_t smb = (uint32_t)__cvta_generic_to_shared(smu);

  int tid = threadIdx.x;
  int warp = tid>>5, lane = tid&31;
  int gq = lane>>2, tig = lane&3;
  int wm = (warp>>1)*32, wn = (warp&1)*32;
  int m0 = blockIdx.y*128, n0 = blockIdx.x*64;

  int ar0 = tid>>2;
  int ac  = (tid&3)*8;
  int acu = (tid&3)*4;

  int lg = lane>>3, lr = lane&7;
  uint32_t aoff[2], boff[2];
  #pragma unroll
  for (int mt=0;mt<2;mt++)
    aoff[mt] = (uint32_t)((wm + mt*16 + (lg&1)*8 + lr)*20 + (lg>>1)*4);
  #pragma unroll
  for (int p=0;p<2;p++)
    boff[p] = (uint32_t)((wn + p*16 + (lg>>1)*8 + lr)*20 + (lg&1)*4);

  float acc[2][4][4];
  #pragma unroll
  for (int mt=0;mt<2;mt++)
    #pragma unroll
    for (int nt=0;nt<4;nt++)
      #pragma unroll
      for (int c=0;c<4;c++) acc[mt][nt][c]=0.f;

  uint4 pah[2], pal[2], pbh, pbl;

  LDTILE(0);
  STTILE(0);
  __syncthreads();

  for (int kt=0; kt<KT; kt++){
    int buf = kt&1;
    if (kt+1 < KT) LDTILE(kt+1);

    uint32_t abase  = smb + (buf*ABUF)*4;
    uint32_t albase = smb + ((2+buf)*ABUF)*4;
    uint32_t bbase  = smb + (4*ABUF + buf*BBUF)*4;
    uint32_t blbase = smb + (4*ABUF + (2+buf)*BBUF)*4;

    #pragma unroll
    for (int kk=0;kk<2;kk++){
      uint32_t ah[2][4], al[2][4];
      #pragma unroll
      for (int mt=0;mt<2;mt++){
        LDSM4(ah[mt][0],ah[mt][1],ah[mt][2],ah[mt][3], abase  + (aoff[mt] + kk*8)*4);
        LDSM4(al[mt][0],al[mt][1],al[mt][2],al[mt][3], albase + (aoff[mt] + kk*8)*4);
      }
      uint32_t bh[2][4], bl[2][4];
      #pragma unroll
      for (int p=0;p<2;p++){
        LDSM4(bh[p][0],bh[p][1],bh[p][2],bh[p][3], bbase  + (boff[p] + kk*8)*4);
        LDSM4(bl[p][0],bl[p][1],bl[p][2],bl[p][3], blbase + (boff[p] + kk*8)*4);
      }
      #pragma unroll
      for (int mt=0;mt<2;mt++)
        #pragma unroll
        for (int p=0;p<2;p++)
          #pragma unroll
          for (int h=0;h<2;h++){
            float* a4 = acc[mt][p*2+h];
            BMMA(a4, ah[mt], bh[p][h*2], bh[p][h*2+1]);
            BMMA(a4, ah[mt], bl[p][h*2], bl[p][h*2+1]);
            BMMA(a4, al[mt], bh[p][h*2], bh[p][h*2+1]);
          }
    }
    if (kt+1 < KT) STTILE(buf^1);
    __syncthreads();
  }

  bool isqk = (MODE==0) && (n0 >= H2);
  #pragma unroll
  for (int mt=0;mt<2;mt++){
    int r0 = m0 + wm + mt*16 + gq;
    #pragma unroll
    for (int nt=0;nt<4;nt++){
      int c0 = n0 + wn + nt*8 + tig*2;
      float b0 = bias[c0], b1 = bias[c0+1];
      #pragma unroll
      for (int h=0;h<2;h++){
        int row = r0 + h*8;
        float v0 = acc[mt][nt][h*2+0] + b0;
        float v1 = acc[mt][nt][h*2+1] + b1;
        if (MODE==2){
          float* p = g_h + (size_t)row*DIM + c0;
          p[0] += v0; p[1] += v1;
        } else if (isqk){
          float* p = g_qk + (size_t)row*QKD + (c0 - H2);
          p[0] = siluf(v0); p[1] = siluf(v1);
        } else {
          float* p = g_hid + (size_t)row*H2 + c0;
          p[0] = siluf(v0); p[1] = siluf(v1);
        }
      }
    }
  }
}

// ---------------- fused quad attention (tensor-core phase B) ---------------
// smem byte map:
//   0       sQK fp32 [256][68]                69632
//   69632   sQQ fp32 [64][68]                 17408
//   87040   sAttH bf16 [64 i][264 j]          33792
//   120832  sAttL bf16 [64 i][264 j]          33792
//   154624  sVh  bf16 [64 j][136 e]           17408
//   172032  sVl  bf16 [64 j][136 e]           17408
//   189440  sG fp32 [384]                      1536
#define SQS 68
#define SAJ 264
#define ATTN_SMEM 190976

__global__ void __launch_bounds__(256) attn_kernel(const float* __restrict__ gamma,
                                                   const float* __restrict__ beta,
                                                   int lay){
  extern __shared__ char smc[];
  float* sQK = (float*)smc;
  float* sQQ = (float*)(smc + 69632);
  __nv_bfloat16* sAh = (__nv_bfloat16*)(smc + 87040);
  __nv_bfloat16* sAl = (__nv_bfloat16*)(smc + 120832);
  __nv_bfloat16* sVh = (__nv_bfloat16*)(smc + 154624);
  __nv_bfloat16* sVl = (__nv_bfloat16*)(smc + 172032);
  float* sG  = (float*)(smc + 189440);
  uint32_t smb = (uint32_t)__cvta_generic_to_shared(smc);

  int it = blockIdx.x, g = blockIdx.y, b = blockIdx.z;
  int tid = threadIdx.x;
  size_t base = (size_t)(b*NG + g)*GRP;
  const float* btab = g_bias8 + (size_t)lay*GRP*GRP;

  #pragma unroll
  for (int i=0;i<16;i++){
    int idx = i*256+tid;
    int r = idx>>4, c4 = (idx&15)*4;
    *(float4*)&sQK[r*SQS + c4] = *(const float4*)(g_qk + (base+r)*QKD + c4);
  }
  if (tid < 64){
    sG[tid]     = gamma[tid];      sG[64+tid]  = beta[tid];        // head 0 (qq)
    sG[128+tid] = gamma[128+tid];  sG[192+tid] = beta[128+tid];    // head 2 (qk)
    sG[256+tid] = gamma[192+tid];  sG[320+tid] = beta[192+tid];    // head 3 (lk)
  }
  __syncthreads();
  #pragma unroll
  for (int i=0;i<16;i++){
    int idx = i*256+tid; int ii = idx>>6, d = idx&63;
    sQQ[ii*SQS+d] = fmaf(sQK[(it*64+ii)*SQS + d], sG[d], sG[64+d]);
  }
  __syncthreads();

  int ty = tid>>5, tx = tid&31;
  // phase A: sim -> laplace -> causal mask -> sAh/sAl [i][j] bf16 hi/lo
  {
    float acc[8][8];
    #pragma unroll
    for (int r=0;r<8;r++)
      #pragma unroll
      for (int c=0;c<8;c++) acc[r][c]=0.f;
    #pragma unroll 4
    for (int d=0; d<64; d++){
      float g2 = sG[128+d], b2 = sG[192+d];
      float a[8], kk[8];
      #pragma unroll
      for (int r=0;r<8;r++) a[r] = sQQ[(ty*8+r)*SQS + d];
      #pragma unroll
      for (int c=0;c<8;c++) kk[c] = fmaf(sQK[(tx + 32*c)*SQS + d], g2, b2);
      #pragma unroll
      for (int r=0;r<8;r++)
        #pragma unroll
        for (int c=0;c<8;c++) acc[r][c] = fmaf(a[r], kk[c], acc[r][c]);
    }
    #pragma unroll
    for (int r=0;r<8;r++){
      int ig = it*64 + ty*8 + r;
      #pragma unroll
      for (int c=0;c<8;c++){
        int j = tx + 32*c;
        float s = acc[r][c]*(1.0f/256.0f) + btab[ig*GRP + j];
        float at = (j <= ig) ? 0.5f*(1.0f + erff((s - 0.70710678f)*0.79788456f)) : 0.0f;
        __nv_bfloat16 h = __float2bfloat16(at);
        sAh[(ty*8+r)*SAJ + j] = h;
        sAl[(ty*8+r)*SAJ + j] = __float2bfloat16(at - __bfloat162float(h));
      }
    }
  }
  __syncthreads();

  float g3r[8], b3r[8];
  #pragma unroll
  for (int r=0;r<8;r++){ g3r[r]=sG[256+ty*8+r]; b3r[r]=sG[320+ty*8+r]; }

  // phase B MMA setup
  int warp = tid>>5, lane = tid&31;
  int lg = lane>>3, lr = lane&7;
  int gq = lane>>2, tig = lane&3;
  int wm_a = (warp&1)*32;       // i offset (2 m16 tiles)
  int wn_e = (warp>>1)*32;      // e offset within 128 chunk (4 n8 tiles)
  uint32_t aoffB[2];
  #pragma unroll
  for (int mt=0;mt<2;mt++)
    aoffB[mt] = (uint32_t)(((wm_a + mt*16 + (lg&1)*8 + lr)*SAJ + (lg>>1)*8)*2);
  uint32_t boffB[2];
  #pragma unroll
  for (int pp=0;pp<2;pp++)
    boffB[pp] = (uint32_t)((((lg&1)*8 + lr)*136 + wn_e + pp*16 + (lg>>1)*8)*2);
  uint32_t Ahb = smb + 87040, Alb = smb + 120832;
  uint32_t Vhb = smb + 154624, Vlb = smb + 172032;

  // staging coords
  int sj = tid>>2, seo = (tid&3)*4;   // j row, e start (steps of 16)
  int sdu = sj*68 + (tid&3)*2;        // u32 dest index

  for (int et=0; et<4; et++){
    float qacc[2][4][4];
    float kvacc[8][4];
    #pragma unroll
    for (int mt=0;mt<2;mt++)
      #pragma unroll
      for (int nt=0;nt<4;nt++)
        #pragma unroll
        for (int c=0;c<4;c++) qacc[mt][nt][c]=0.f;
    #pragma unroll
    for (int r=0;r<8;r++)
      #pragma unroll
      for (int c=0;c<4;c++) kvacc[r][c]=0.f;

    for (int jc=0; jc<4; jc++){
      __syncthreads();
      {
        const float* src = g_hid + (base + jc*64 + sj)*H2 + et*128 + seo;
        uint32_t* dh = (uint32_t*)sVh;
        uint32_t* dl = (uint32_t*)sVl;
        #pragma unroll
        for (int i=0;i<8;i++){
          float4 v = *(const float4*)(src + i*16);
          uint32_t h01 = bpack(v.x, v.y);
          uint32_t h23 = bpack(v.z, v.w);
          float hx = __uint_as_float(h01<<16);
          float hy = __uint_as_float(h01 & 0xffff0000u);
          float hz = __uint_as_float(h23<<16);
          float hw = __uint_as_float(h23 & 0xffff0000u);
          uint32_t l01 = bpack(v.x-hx, v.y-hy);
          uint32_t l23 = bpack(v.z-hz, v.w-hw);
          dh[sdu + i*8]     = h01;  dh[sdu + i*8 + 1] = h23;
          dl[sdu + i*8]     = l01;  dl[sdu + i*8 + 1] = l23;
        }
      }
      __syncthreads();

      #pragma unroll
      for (int ks=0; ks<4; ks++){
        uint32_t kA = (uint32_t)((jc*64 + ks*16)*2);
        uint32_t kB = (uint32_t)(ks*16*272);
        uint32_t ah[2][4], al[2][4];
        #pragma unroll
        for (int mt=0;mt<2;mt++){
          LDSM4(ah[mt][0],ah[mt][1],ah[mt][2],ah[mt][3], Ahb + aoffB[mt] + kA);
          LDSM4(al[mt][0],al[mt][1],al[mt][2],al[mt][3], Alb + aoffB[mt] + kA);
        }
        uint32_t bh[2][4], bl[2][4];
        #pragma unroll
        for (int pp=0;pp<2;pp++){
          LDSM4T(bh[pp][0],bh[pp][1],bh[pp][2],bh[pp][3], Vhb + boffB[pp] + kB);
          LDSM4T(bl[pp][0],bl[pp][1],bl[pp][2],bl[pp][3], Vlb + boffB[pp] + kB);
        }
        #pragma unroll
        for (int mt=0;mt<2;mt++)
          #pragma unroll
          for (int pp=0;pp<2;pp++)
            #pragma unroll
            for (int h=0;h<2;h++){
              float* a4 = qacc[mt][pp*2+h];
              BMMA(a4, ah[mt], bh[pp][h*2], bh[pp][h*2+1]);
              BMMA(a4, ah[mt], bl[pp][h*2], bl[pp][h*2+1]);
              BMMA(a4, al[mt], bh[pp][h*2], bh[pp][h*2+1]);
            }
      }

      if (it==0){
        const uint32_t* vh = (const uint32_t*)sVh;
        const uint32_t* vl = (const uint32_t*)sVl;
        #pragma unroll 2
        for (int jj=0;jj<64;jj++){
          uint32_t h01 = vh[jj*68 + tx*2], h23 = vh[jj*68 + tx*2 + 1];
          uint32_t l01 = vl[jj*68 + tx*2], l23 = vl[jj*68 + tx*2 + 1];
          float vx = __uint_as_float(h01<<16) + __uint_as_float(l01<<16);
          float vy = __uint_as_float(h01&0xffff0000u) + __uint_as_float(l01&0xffff0000u);
          float vz = __uint_as_float(h23<<16) + __uint_as_float(l23<<16);
          float vw = __uint_as_float(h23&0xffff0000u) + __uint_as_float(l23&0xffff0000u);
          int j = jc*64 + jj;
          float4 q0 = *(float4*)&sQK[j*SQS + ty*8];
          float4 q1 = *(float4*)&sQK[j*SQS + ty*8 + 4];
          float qv[8] = {q0.x,q0.y,q0.z,q0.w,q1.x,q1.y,q1.z,q1.w};
          #pragma unroll
          for (int r=0;r<8;r++){
            float lk = fmaf(qv[r], g3r[r], b3r[r]);
            kvacc[r][0]=fmaf(lk,vx,kvacc[r][0]);
            kvacc[r][1]=fmaf(lk,vy,kvacc[r][1]);
            kvacc[r][2]=fmaf(lk,vz,kvacc[r][2]);
            kvacc[r][3]=fmaf(lk,vw,kvacc[r][3]);
          }
        }
      }
    }

    // write quad
    #pragma unroll
    for (int mt=0;mt<2;mt++)
      #pragma unroll
      for (int nt=0;nt<4;nt++){
        size_t row = base + it*64 + wm_a + mt*16 + gq;
        int e = et*128 + wn_e + nt*8 + tig*2;
        float2 o0; o0.x = qacc[mt][nt][0]; o0.y = qacc[mt][nt][1];
        float2 o1; o1.x = qacc[mt][nt][2]; o1.y = qacc[mt][nt][3];
        *(float2*)(g_quad + row*HIDW + e) = o0;
        *(float2*)(g_quad + (row+8)*HIDW + e) = o1;
      }
    if (it==0){
      #pragma unroll
      for (int r=0;r<8;r++){
        float4 o;
        o.x=kvacc[r][0]*(1.0f/256.0f); o.y=kvacc[r][1]*(1.0f/256.0f);
        o.z=kvacc[r][2]*(1.0f/256.0f); o.w=kvacc[r][3]*(1.0f/256.0f);
        *(float4*)(g_kv + ((size_t)(b*NG+g)*QKD + ty*8 + r)*HIDW + et*128 + tx*4) = o;
      }
    }
  }
}

// ---------------- exclusive cumsum of kv over groups (in place) ------------
__global__ void cumsum_kernel(){
  int b = blockIdx.y;
  int idx = blockIdx.x*256 + threadIdx.x;
  float acc = 0.f;
  #pragma unroll
  for (int g=0; g<NG; g++){
    size_t p = ((size_t)(b*NG+g))*(QKD*HIDW) + idx;
    float cur = g_kv[p];
    g_kv[p] = acc;
    acc += cur;
  }
}

// ---------------- linear attention + gated combine (writes bf16 splits) ----
#define LIN_SMEM ((64*64 + 64*128 + 128)*4)
__global__ void __launch_bounds__(256) lin_kernel(const float* __restrict__ gamma,
                                                  const float* __restrict__ beta){
  extern __shared__ float sm[];
  float* sLQ  = sm;
  float* sLKV = sLQ + 64*64;
  float* sG1  = sLKV + 64*128;
  float* sB1  = sG1 + 64;
  int et = blockIdx.x & 3, it = blockIdx.x >> 2;
  int g = blockIdx.y, b = blockIdx.z;
  int tid = threadIdx.x, ty = tid>>5, tx = tid&31;
  size_t base = (size_t)(b*NG+g)*GRP;

  if (tid < 64){ sG1[tid]=gamma[64+tid]; sB1[tid]=beta[64+tid]; }
  #pragma unroll
  for (int i=0;i<4;i++){
    int idx = i*256+tid; int r = idx>>4, c4 = (idx&15)*4;
    *(float4*)&sLQ[r*64+c4] = *(const float4*)(g_qk + (base + it*64 + r)*QKD + c4);
  }
  #pragma unroll
  for (int i=0;i<8;i++){
    int idx=i*256+tid; int r=idx>>5, c4=(idx&31)*4;
    *(float4*)&sLKV[r*128+c4] = *(const float4*)(g_kv + ((size_t)(b*NG+g)*QKD + r)*HIDW + et*128 + c4);
  }
  __syncthreads();
  #pragma unroll
  for (int i=0;i<16;i++){
    int idx=i*256+tid; int r=idx>>6, d=idx&63;
    sLQ[r*64+d] = fmaf(sLQ[r*64+d], sG1[d], sB1[d]);
  }
  __syncthreads();

  float acc[8][4];
  #pragma unroll
  for (int r=0;r<8;r++){ acc[r][0]=0.f; acc[r][1]=0.f; acc[r][2]=0.f; acc[r][3]=0.f; }
  #pragma unroll 4
  for (int d=0; d<64; d++){
    float4 kv4 = *(float4*)&sLKV[d*128 + tx*4];
    float a[8];
    #pragma unroll
    for (int r=0;r<8;r++) a[r] = sLQ[(ty*8+r)*64 + d];
    #pragma unroll
    for (int r=0;r<8;r++){
      acc[r][0]=fmaf(a[r],kv4.x,acc[r][0]);
      acc[r][1]=fmaf(a[r],kv4.y,acc[r][1]);
      acc[r][2]=fmaf(a[r],kv4.z,acc[r][2]);
      acc[r][3]=fmaf(a[r],kv4.w,acc[r][3]);
    }
  }
  #pragma unroll
  for (int r=0;r<8;r++){
    size_t row = base + it*64 + ty*8 + r;
    int e = et*128 + tx*4;
    float4 q  = *(float4*)(g_quad + row*HIDW + e);
    float4 gt = *(float4*)(g_hid + row*H2 + HIDW + e);
    float o[4];
    o[0] = gt.x*(q.x+acc[r][0]);
    o[1] = gt.y*(q.y+acc[r][1]);
    o[2] = gt.z*(q.z+acc[r][2]);
    o[3] = gt.w*(q.w+acc[r][3]);
    size_t p = row*HIDW + e;
    #pragma unroll
    for (int c=0;c<4;c++){
      __nv_bfloat16 h = __float2bfloat16(o[c]);
      g_aqh[p+c] = h;
      g_aql[p+c] = __float2bfloat16(o[c] - __bfloat162float(h));
    }
  }
}

// ---------------- final mean pool + classifier -----------------------------
__global__ void mean1_kernel(){
  int c = blockIdx.x, b = blockIdx.y, d = threadIdx.x;
  float s = 0.f;
  size_t rb = (size_t)b*8192 + (size_t)c*256;
  for (int r=0;r<256;r++) s += g_h[(rb+r)*DIM + d];
  g_part[(b*NG+c)*DIM + d] = s;
}

__global__ void head_kernel(const float* __restrict__ Wd, const float* __restrict__ bd,
                            float* __restrict__ out){
  int b = blockIdx.x, d = threadIdx.x;
  float s = 0.f;
  for (int c=0;c<NG;c++) s += g_part[(b*NG+c)*DIM + d];
  s *= (1.0f/8192.0f);
  __shared__ float r0[256], r1[256];
  r0[d] = s*Wd[d*2+0];
  r1[d] = s*Wd[d*2+1];
  __syncthreads();
  for (int o=128;o>0;o>>=1){
    if (d<o){ r0[d]+=r0[d+o]; r1[d]+=r1[d+o]; }
    __syncthreads();
  }
  if (d==0){ out[b*2+0]=r0[0]+bd[0]; out[b*2+1]=r1[0]+bd[1]; }
}

// ---------------- host ------------------------------------------------------
extern "C" void kernel_launch(void* const* d_in, const int* in_sizes, int n_in,
                              void* d_out, int out_size){
  const float* x      = (const float*)d_in[0];
  const float* W_emb  = (const float*)d_in[1];
  const float* b_emb  = (const float*)d_in[2];
  const float* pos    = (const float*)d_in[3];
  const float* ln_g   = (const float*)d_in[4];
  const float* ln_b   = (const float*)d_in[5];
  const float* Wh     = (const float*)d_in[6];
  const float* bh     = (const float*)d_in[7];
  const float* Wqk    = (const float*)d_in[8];
  const float* bqk    = (const float*)d_in[9];
  const float* gamma  = (const float*)d_in[10];
  const float* beta   = (const float*)d_in[11];
  const float* relb   = (const float*)d_in[12];
  const float* Wo     = (const float*)d_in[13];
  const float* bo     = (const float*)d_in[14];
  const float* Wd     = (const float*)d_in[15];
  const float* bd     = (const float*)d_in[16];
  float* out = (float*)d_out;

  cudaFuncSetAttribute(attn_kernel, cudaFuncAttributeMaxDynamicSharedMemorySize, ATTN_SMEM);
  cudaFuncSetAttribute(lin_kernel,  cudaFuncAttributeMaxDynamicSharedMemorySize, LIN_SMEM);
  cudaFuncSetAttribute(mma_gemm<0>, cudaFuncAttributeMaxDynamicSharedMemorySize, GSM);
  cudaFuncSetAttribute(mma_gemm<2>, cudaFuncAttributeMaxDynamicSharedMemorySize, GSM);

  wprep_all<<<dim3(32, 16, NLAYER*3), dim3(32,8)>>>(Wh, Wqk, Wo);
  misc_prep<<<dim3(GRP, NLAYER), GRP>>>(relb, bh, bqk);
  embed_ln_kernel<<<TOK,256>>>(x, W_emb, b_emb, pos, ln_g, ln_b);

  for (int l=0;l<NLAYER;l++){
    int base = l*WLAYER;
    if (l > 0) ln_kernel<<<TOK,256>>>(ln_g + l*DIM, ln_b + l*DIM);
    mma_gemm<0><<<dim3(NCAT/64, TOK/128), 256, GSM>>>(base, nullptr, l);
    attn_kernel<<<dim3(4,NG,NBATCH),256,ATTN_SMEM>>>(gamma + l*256, beta + l*256, l);
    cumsum_kernel<<<dim3(128,NBATCH),256>>>();
    lin_kernel<<<dim3(16,NG,NBATCH),256,LIN_SMEM>>>(gamma + l*256, beta + l*256);
    mma_gemm<2><<<dim3(DIM/64, TOK/128), 256, GSM>>>(base + NCAT*DIM, bo + l*DIM, l);
  }
  mean1_kernel<<<dim3(NG,NBATCH),256>>>();
  head_kernel<<<NBATCH,256>>>(Wd, bd, out);
}